// round 6
// baseline (speedup 1.0000x reference)
#include <cuda_runtime.h>
#include <math.h>

#define B_   4
#define S_   2048
#define DM   1024
#define NH   16
#define DK   64
#define BS_  (B_*S_)   // 8192

// Scratch (device globals -- no allocation allowed)
__device__ float g_Qp[(size_t)BS_*DM];
__device__ float g_Kp[(size_t)BS_*DM];
__device__ float g_Vp[(size_t)BS_*DM];
__device__ float g_Ao[(size_t)BS_*DM];

// ---------------------------------------------------------------------------
// SGEMM: C[M,N] = A[M,K] * B[K,N], all row-major. Tile 128x64x16, 8x4 micro.
// ---------------------------------------------------------------------------
#define BM 128
#define BN 64
#define BK 16

__global__ __launch_bounds__(256) void sgemm_kernel(
    const float* __restrict__ A, const float* __restrict__ Bm,
    float* __restrict__ C, int M, int N, int K)
{
    __shared__ float As[BK][BM];
    __shared__ float Bs[BK][BN];

    int t  = threadIdx.x;
    int m0 = blockIdx.y * BM;
    int n0 = blockIdx.x * BN;
    int ty = t >> 4;        // 0..15
    int tx = t & 15;        // 0..15

    float acc[8][4];
    #pragma unroll
    for (int i = 0; i < 8; i++)
        #pragma unroll
        for (int j = 0; j < 4; j++) acc[i][j] = 0.f;

    int arow = t >> 2;          // 0..63
    int acol = (t & 3) * 4;     // 0,4,8,12
    int brow = t >> 4;          // 0..15
    int bcol = (t & 15) * 4;    // 0..60

    for (int k0 = 0; k0 < K; k0 += BK) {
        #pragma unroll
        for (int r = 0; r < 2; r++) {
            int row = arow + r * 64;
            float4 a = *(const float4*)&A[(size_t)(m0 + row) * K + k0 + acol];
            As[acol + 0][row] = a.x;
            As[acol + 1][row] = a.y;
            As[acol + 2][row] = a.z;
            As[acol + 3][row] = a.w;
        }
        float4 bv = *(const float4*)&Bm[(size_t)(k0 + brow) * N + n0 + bcol];
        *(float4*)&Bs[brow][bcol] = bv;
        __syncthreads();

        #pragma unroll
        for (int k = 0; k < BK; k++) {
            float ra[8], rb[4];
            *(float4*)(ra)     = *(const float4*)&As[k][ty * 8];
            *(float4*)(ra + 4) = *(const float4*)&As[k][ty * 8 + 4];
            *(float4*)(rb)     = *(const float4*)&Bs[k][tx * 4];
            #pragma unroll
            for (int i = 0; i < 8; i++)
                #pragma unroll
                for (int j = 0; j < 4; j++)
                    acc[i][j] += ra[i] * rb[j];
        }
        __syncthreads();
    }

    #pragma unroll
    for (int i = 0; i < 8; i++) {
        float4 v = make_float4(acc[i][0], acc[i][1], acc[i][2], acc[i][3]);
        *(float4*)&C[(size_t)(m0 + ty * 8 + i) * N + n0 + tx * 4] = v;
    }
}

// ---------------------------------------------------------------------------
// RoPE (interleaved pairs within each 64-dim head), in-place.
// X layout: [b*s][h*64 + d]
// ---------------------------------------------------------------------------
__global__ void rope_kernel(float* __restrict__ X)
{
    int idx = blockIdx.x * blockDim.x + threadIdx.x;  // pair index
    const int total = BS_ * NH * (DK / 2);
    if (idx >= total) return;

    int p    = idx & 31;        // pair index within head (0..31)
    int rest = idx >> 5;        // bs*NH + h
    int bs   = rest / NH;
    int s    = bs % S_;

    float inv = (float)pow(10000.0, -(double)(2 * p) / (double)DK);
    float ang = (float)s * inv;
    float sn, cs;
    sincosf(ang, &sn, &cs);

    float* base = X + (size_t)rest * DK + 2 * p;
    float x1 = base[0], x2 = base[1];
    base[0] = x1 * cs - x2 * sn;
    base[1] = x1 * sn + x2 * cs;
}

// ---------------------------------------------------------------------------
// Flash-style attention. Grid: (S/128, B*NH). Block: 128 threads, 1 query each.
// Dynamic shared: Ks[64*64] + Vs[64*64] + Sc[64*128] = 64 KB.
// ---------------------------------------------------------------------------
__global__ __launch_bounds__(128) void attn_kernel(
    const float* __restrict__ Q, const float* __restrict__ K,
    const float* __restrict__ V, float* __restrict__ O)
{
    extern __shared__ float sm[];
    float* Ks = sm;                 // 64*64
    float* Vs = sm + 64 * 64;       // 64*64
    float* Sc = sm + 2 * 64 * 64;   // 64*128

    int tid = threadIdx.x;
    int bh  = blockIdx.y;
    int b   = bh >> 4;
    int h   = bh & 15;
    int q   = blockIdx.x * 128 + tid;

    const float scale = 0.125f;  // 1/sqrt(64)

    float4 qv[16];
    {
        const float* qb = Q + (((size_t)(b * S_ + q)) * NH + h) * DK;
        #pragma unroll
        for (int i = 0; i < 16; i++) {
            float4 tq = *(const float4*)(qb + i * 4);
            qv[i] = make_float4(tq.x * scale, tq.y * scale, tq.z * scale, tq.w * scale);
        }
    }
    float4 av[16];
    #pragma unroll
    for (int i = 0; i < 16; i++) av[i] = make_float4(0.f, 0.f, 0.f, 0.f);
    float mval = -1e30f, lval = 0.f;

    int jrow  = tid >> 1;          // 0..63
    int jcol0 = (tid & 1) * 32;    // 0 or 32

    for (int t0 = 0; t0 < S_; t0 += 64) {
        const float* kb = K + (((size_t)(b * S_ + t0 + jrow)) * NH + h) * DK + jcol0;
        const float* vb = V + (((size_t)(b * S_ + t0 + jrow)) * NH + h) * DK + jcol0;
        #pragma unroll
        for (int u = 0; u < 8; u++) {
            *(float4*)&Ks[jrow * 64 + jcol0 + u * 4] = *(const float4*)(kb + u * 4);
            *(float4*)&Vs[jrow * 64 + jcol0 + u * 4] = *(const float4*)(vb + u * 4);
        }
        __syncthreads();

        // Pass 1: scores for 64 keys + tile max
        float tmax = -1e30f;
        #pragma unroll 4
        for (int j = 0; j < 64; j++) {
            const float4* kr = (const float4*)&Ks[j * 64];
            float s = 0.f;
            #pragma unroll
            for (int i = 0; i < 16; i++) {
                float4 kk = kr[i];
                s += qv[i].x * kk.x + qv[i].y * kk.y + qv[i].z * kk.z + qv[i].w * kk.w;
            }
            Sc[j * 128 + tid] = s;
            tmax = fmaxf(tmax, s);
        }

        float mnew = fmaxf(mval, tmax);
        float corr = __expf(mval - mnew);
        lval *= corr;
        #pragma unroll
        for (int i = 0; i < 16; i++) {
            av[i].x *= corr; av[i].y *= corr; av[i].z *= corr; av[i].w *= corr;
        }
        mval = mnew;

        // Pass 2: exp + PV accumulate
        #pragma unroll 4
        for (int j = 0; j < 64; j++) {
            float p = __expf(Sc[j * 128 + tid] - mval);
            lval += p;
            const float4* vr = (const float4*)&Vs[j * 64];
            #pragma unroll
            for (int i = 0; i < 16; i++) {
                float4 vv = vr[i];
                av[i].x += p * vv.x; av[i].y += p * vv.y;
                av[i].z += p * vv.z; av[i].w += p * vv.w;
            }
        }
        __syncthreads();
    }

    float inv = 1.f / lval;
    float* ob = O + (((size_t)(b * S_ + q)) * NH + h) * DK;
    #pragma unroll
    for (int i = 0; i < 16; i++) {
        float4 v = av[i];
        ((float4*)ob)[i] = make_float4(v.x * inv, v.y * inv, v.z * inv, v.w * inv);
    }
}

// ---------------------------------------------------------------------------
extern "C" void kernel_launch(void* const* d_in, const int* in_sizes, int n_in,
                              void* d_out, int out_size)
{
    const float* q  = (const float*)d_in[0];
    const float* k  = (const float*)d_in[1];
    const float* v  = (const float*)d_in[2];
    const float* Wq = (const float*)d_in[3];
    const float* Wk = (const float*)d_in[4];
    const float* Wv = (const float*)d_in[5];
    const float* Wo = (const float*)d_in[6];
    float* out = (float*)d_out;

    float *Qp, *Kp, *Vp, *Ao;
    cudaGetSymbolAddress((void**)&Qp, g_Qp);
    cudaGetSymbolAddress((void**)&Kp, g_Kp);
    cudaGetSymbolAddress((void**)&Vp, g_Vp);
    cudaGetSymbolAddress((void**)&Ao, g_Ao);

    dim3 gblk(DM / BN, BS_ / BM);   // (16, 64)
    sgemm_kernel<<<gblk, 256>>>(q, Wq, Qp, BS_, DM, DM);
    sgemm_kernel<<<gblk, 256>>>(k, Wk, Kp, BS_, DM, DM);
    sgemm_kernel<<<gblk, 256>>>(v, Wv, Vp, BS_, DM, DM);

    const int total_pairs = BS_ * NH * (DK / 2);
    int rblocks = (total_pairs + 255) / 256;
    rope_kernel<<<rblocks, 256>>>(Qp);
    rope_kernel<<<rblocks, 256>>>(Kp);

    const int ATTN_SMEM = (2 * 64 * 64 + 64 * 128) * sizeof(float);  // 64 KB
    cudaFuncSetAttribute(attn_kernel, cudaFuncAttributeMaxDynamicSharedMemorySize, ATTN_SMEM);
    dim3 ablk(S_ / 128, B_ * NH);   // (16, 64)
    attn_kernel<<<ablk, 128, ATTN_SMEM>>>(Qp, Kp, Vp, Ao);

    sgemm_kernel<<<gblk, 256>>>(Ao, Wo, out, BS_, DM, DM);
}

// round 7
// speedup vs baseline: 1.0727x; 1.0727x over previous
#include <cuda_runtime.h>
#include <math.h>

#define B_   4
#define S_   2048
#define DM   1024
#define NH   16
#define DK   64
#define BS_  (B_*S_)   // 8192

typedef unsigned long long ull;

// Scratch (device globals -- no allocation allowed)
__device__ float g_Qp[(size_t)BS_*DM];
__device__ float g_Kp[(size_t)BS_*DM];
__device__ float g_Vp[(size_t)BS_*DM];
__device__ float g_Ao[(size_t)BS_*DM];
__device__ float2 g_rope[S_ * (DK/2)];   // [s][p] -> (cos, sin)

// ---------------------------------------------------------------------------
// Packed fp32x2 helpers (Blackwell FFMA2 path — only reachable via PTX)
// ---------------------------------------------------------------------------
__device__ __forceinline__ ull ffma2(ull a, ull b, ull c) {
    ull d;
    asm("fma.rn.f32x2 %0, %1, %2, %3;" : "=l"(d) : "l"(a), "l"(b), "l"(c));
    return d;
}
__device__ __forceinline__ ull fmul2(ull a, ull b) {
    ull d;
    asm("mul.rn.f32x2 %0, %1, %2;" : "=l"(d) : "l"(a), "l"(b));
    return d;
}
__device__ __forceinline__ ull fadd2(ull a, ull b) {
    ull d;
    asm("add.rn.f32x2 %0, %1, %2;" : "=l"(d) : "l"(a), "l"(b));
    return d;
}
__device__ __forceinline__ ull fpack2(float lo, float hi) {
    ull d;
    asm("mov.b64 %0, {%1, %2};" : "=l"(d) : "f"(lo), "f"(hi));
    return d;
}
__device__ __forceinline__ float2 funpack2(ull v) {
    float lo, hi;
    asm("mov.b64 {%0, %1}, %2;" : "=f"(lo), "=f"(hi) : "l"(v));
    return make_float2(lo, hi);
}

// ---------------------------------------------------------------------------
// SGEMM: C[M,N] = A[M,K] * B[K,N], row-major. Tile 128x64x16, 8x4 micro,
// inner product via packed f32x2 FMA (B duplicated in smem so both operands
// load as natural 64-bit pairs).
// ---------------------------------------------------------------------------
#define BM 128
#define BN 64
#define BK 16

__global__ __launch_bounds__(256) void sgemm_kernel(
    const float* __restrict__ A, const float* __restrict__ Bm,
    float* __restrict__ C, int M, int N, int K)
{
    __shared__ float As[BK][BM];        // 8 KB
    __shared__ float Bd[BK][BN * 2];    // 8 KB, each value duplicated

    int t  = threadIdx.x;
    int m0 = blockIdx.y * BM;
    int n0 = blockIdx.x * BN;
    int ty = t >> 4;        // 0..15
    int tx = t & 15;        // 0..15

    ull acc2[4][4];         // acc2[ip][j]: rows (2ip, 2ip+1) x col j
    #pragma unroll
    for (int ip = 0; ip < 4; ip++)
        #pragma unroll
        for (int j = 0; j < 4; j++) acc2[ip][j] = 0ull;

    int arow = t >> 2;          // 0..63
    int acol = (t & 3) * 4;     // 0,4,8,12
    int brow = t >> 4;          // 0..15
    int bcol = (t & 15) * 4;    // 0..60

    for (int k0 = 0; k0 < K; k0 += BK) {
        #pragma unroll
        for (int r = 0; r < 2; r++) {
            int row = arow + r * 64;
            float4 a = *(const float4*)&A[(size_t)(m0 + row) * K + k0 + acol];
            As[acol + 0][row] = a.x;
            As[acol + 1][row] = a.y;
            As[acol + 2][row] = a.z;
            As[acol + 3][row] = a.w;
        }
        {
            float4 bv = *(const float4*)&Bm[(size_t)(k0 + brow) * N + n0 + bcol];
            *(float4*)&Bd[brow][2 * bcol]     = make_float4(bv.x, bv.x, bv.y, bv.y);
            *(float4*)&Bd[brow][2 * bcol + 4] = make_float4(bv.z, bv.z, bv.w, bv.w);
        }
        __syncthreads();

        #pragma unroll
        for (int k = 0; k < BK; k++) {
            ulonglong2 a01 = *(const ulonglong2*)&As[k][ty * 8];
            ulonglong2 a23 = *(const ulonglong2*)&As[k][ty * 8 + 4];
            ulonglong2 b01 = *(const ulonglong2*)&Bd[k][tx * 8];
            ulonglong2 b23 = *(const ulonglong2*)&Bd[k][tx * 8 + 4];
            ull ra[4] = {a01.x, a01.y, a23.x, a23.y};   // natural row pairs
            ull rb[4] = {b01.x, b01.y, b23.x, b23.y};   // duplicated cols
            #pragma unroll
            for (int ip = 0; ip < 4; ip++)
                #pragma unroll
                for (int j = 0; j < 4; j++)
                    acc2[ip][j] = ffma2(ra[ip], rb[j], acc2[ip][j]);
        }
        __syncthreads();
    }

    #pragma unroll
    for (int ip = 0; ip < 4; ip++) {
        float2 v0 = funpack2(acc2[ip][0]);
        float2 v1 = funpack2(acc2[ip][1]);
        float2 v2 = funpack2(acc2[ip][2]);
        float2 v3 = funpack2(acc2[ip][3]);
        *(float4*)&C[(size_t)(m0 + ty * 8 + 2 * ip) * N + n0 + tx * 4]
            = make_float4(v0.x, v1.x, v2.x, v3.x);
        *(float4*)&C[(size_t)(m0 + ty * 8 + 2 * ip + 1) * N + n0 + tx * 4]
            = make_float4(v0.y, v1.y, v2.y, v3.y);
    }
}

// ---------------------------------------------------------------------------
// RoPE split in two: a tiny table kernel (the only fp64 pow work: 65536
// entries, 64x fewer than per-element) + a memory-bound apply kernel.
// ---------------------------------------------------------------------------
__global__ void rope_table_kernel()
{
    int idx = blockIdx.x * blockDim.x + threadIdx.x;
    if (idx >= S_ * (DK / 2)) return;
    int p = idx & 31;
    int s = idx >> 5;
    double inv = pow(10000.0, -(double)(2 * p) / (double)DK);
    float ang = (float)s * (float)inv;
    float sn, cs;
    sincosf(ang, &sn, &cs);
    g_rope[idx] = make_float2(cs, sn);
}

__global__ void rope_apply_kernel(float* __restrict__ X)
{
    int idx = blockIdx.x * blockDim.x + threadIdx.x;  // pair index
    const int total = BS_ * NH * (DK / 2);
    if (idx >= total) return;

    int p    = idx & 31;          // pair within head
    int rest = idx >> 5;          // bs*NH + h
    int s    = (rest >> 4) & (S_ - 1);

    float2 cs = g_rope[s * 32 + p];
    float2* base = (float2*)(X + (size_t)rest * DK) + p;
    float2 x = *base;
    *base = make_float2(x.x * cs.x - x.y * cs.y,
                        x.x * cs.y + x.y * cs.x);
}

// ---------------------------------------------------------------------------
// Flash-style attention, inner loops in packed f32x2.
// Grid: (S/128, B*NH). Block: 128 threads, 1 query each.
// Dynamic shared: Ks[64*64] + Vs[64*64] + Sc[64*128] = 64 KB.
// ---------------------------------------------------------------------------
__global__ __launch_bounds__(128) void attn_kernel(
    const float* __restrict__ Q, const float* __restrict__ K,
    const float* __restrict__ V, float* __restrict__ O)
{
    extern __shared__ float sm[];
    float* Ks = sm;                 // 64*64
    float* Vs = sm + 64 * 64;       // 64*64
    float* Sc = sm + 2 * 64 * 64;   // 64*128

    int tid = threadIdx.x;
    int bh  = blockIdx.y;
    int b   = bh >> 4;
    int h   = bh & 15;
    int q   = blockIdx.x * 128 + tid;

    const float scale = 0.125f;  // 1/sqrt(64)
    const ull scale2 = fpack2(scale, scale);

    ull qv[32];   // 64 floats as 32 pairs, pre-scaled
    {
        const ulonglong2* qb =
            (const ulonglong2*)(Q + (((size_t)(b * S_ + q)) * NH + h) * DK);
        #pragma unroll
        for (int i = 0; i < 16; i++) {
            ulonglong2 t2 = qb[i];
            qv[2 * i]     = fmul2(t2.x, scale2);
            qv[2 * i + 1] = fmul2(t2.y, scale2);
        }
    }
    ull av[32];
    #pragma unroll
    for (int i = 0; i < 32; i++) av[i] = 0ull;
    float mval = -1e30f, lval = 0.f;

    int jrow  = tid >> 1;          // 0..63
    int jcol0 = (tid & 1) * 32;    // 0 or 32

    for (int t0 = 0; t0 < S_; t0 += 64) {
        const float* kb = K + (((size_t)(b * S_ + t0 + jrow)) * NH + h) * DK + jcol0;
        const float* vb = V + (((size_t)(b * S_ + t0 + jrow)) * NH + h) * DK + jcol0;
        #pragma unroll
        for (int u = 0; u < 8; u++) {
            *(float4*)&Ks[jrow * 64 + jcol0 + u * 4] = *(const float4*)(kb + u * 4);
            *(float4*)&Vs[jrow * 64 + jcol0 + u * 4] = *(const float4*)(vb + u * 4);
        }
        __syncthreads();

        // Pass 1: scores (packed dot products) + tile max
        float tmax = -1e30f;
        #pragma unroll 2
        for (int j = 0; j < 64; j++) {
            const ulonglong2* kr = (const ulonglong2*)&Ks[j * 64];
            ull d0 = 0ull, d1 = 0ull, d2 = 0ull, d3 = 0ull;
            #pragma unroll
            for (int i = 0; i < 8; i++) {
                ulonglong2 ka = kr[2 * i];
                ulonglong2 kbv = kr[2 * i + 1];
                d0 = ffma2(qv[4 * i],     ka.x,  d0);
                d1 = ffma2(qv[4 * i + 1], ka.y,  d1);
                d2 = ffma2(qv[4 * i + 2], kbv.x, d2);
                d3 = ffma2(qv[4 * i + 3], kbv.y, d3);
            }
            float2 r = funpack2(fadd2(fadd2(d0, d1), fadd2(d2, d3)));
            float s = r.x + r.y;
            Sc[j * 128 + tid] = s;
            tmax = fmaxf(tmax, s);
        }

        float mnew = fmaxf(mval, tmax);
        float corr = __expf(mval - mnew);
        lval *= corr;
        {
            ull corr2 = fpack2(corr, corr);
            #pragma unroll
            for (int i = 0; i < 32; i++) av[i] = fmul2(av[i], corr2);
        }
        mval = mnew;

        // Pass 2: exp + packed PV accumulate
        #pragma unroll 2
        for (int j = 0; j < 64; j++) {
            float p = __expf(Sc[j * 128 + tid] - mval);
            lval += p;
            ull p2 = fpack2(p, p);
            const ulonglong2* vr = (const ulonglong2*)&Vs[j * 64];
            #pragma unroll
            for (int i = 0; i < 16; i++) {
                ulonglong2 vv = vr[i];
                av[2 * i]     = ffma2(p2, vv.x, av[2 * i]);
                av[2 * i + 1] = ffma2(p2, vv.y, av[2 * i + 1]);
            }
        }
        __syncthreads();
    }

    float inv = 1.f / lval;
    ull inv2 = fpack2(inv, inv);
    ulonglong2* ob = (ulonglong2*)(O + (((size_t)(b * S_ + q)) * NH + h) * DK);
    #pragma unroll
    for (int i = 0; i < 16; i++) {
        ulonglong2 v2;
        v2.x = fmul2(av[2 * i], inv2);
        v2.y = fmul2(av[2 * i + 1], inv2);
        ob[i] = v2;
    }
}

// ---------------------------------------------------------------------------
extern "C" void kernel_launch(void* const* d_in, const int* in_sizes, int n_in,
                              void* d_out, int out_size)
{
    const float* q  = (const float*)d_in[0];
    const float* k  = (const float*)d_in[1];
    const float* v  = (const float*)d_in[2];
    const float* Wq = (const float*)d_in[3];
    const float* Wk = (const float*)d_in[4];
    const float* Wv = (const float*)d_in[5];
    const float* Wo = (const float*)d_in[6];
    float* out = (float*)d_out;

    float *Qp, *Kp, *Vp, *Ao;
    cudaGetSymbolAddress((void**)&Qp, g_Qp);
    cudaGetSymbolAddress((void**)&Kp, g_Kp);
    cudaGetSymbolAddress((void**)&Vp, g_Vp);
    cudaGetSymbolAddress((void**)&Ao, g_Ao);

    // RoPE table first (independent of projections)
    rope_table_kernel<<<(S_ * 32 + 255) / 256, 256>>>();

    dim3 gblk(DM / BN, BS_ / BM);   // (16, 64)
    sgemm_kernel<<<gblk, 256>>>(q, Wq, Qp, BS_, DM, DM);
    sgemm_kernel<<<gblk, 256>>>(k, Wk, Kp, BS_, DM, DM);
    sgemm_kernel<<<gblk, 256>>>(v, Wv, Vp, BS_, DM, DM);

    const int total_pairs = BS_ * NH * (DK / 2);
    int rblocks = (total_pairs + 255) / 256;
    rope_apply_kernel<<<rblocks, 256>>>(Qp);
    rope_apply_kernel<<<rblocks, 256>>>(Kp);

    const int ATTN_SMEM = (2 * 64 * 64 + 64 * 128) * sizeof(float);  // 64 KB
    cudaFuncSetAttribute(attn_kernel, cudaFuncAttributeMaxDynamicSharedMemorySize, ATTN_SMEM);
    dim3 ablk(S_ / 128, B_ * NH);   // (16, 64)
    attn_kernel<<<ablk, 128, ATTN_SMEM>>>(Qp, Kp, Vp, Ao);

    sgemm_kernel<<<gblk, 256>>>(Ao, Wo, out, BS_, DM, DM);
}

// round 12
// speedup vs baseline: 1.6690x; 1.5559x over previous
#include <cuda_runtime.h>
#include <cuda_bf16.h>
#include <math.h>
#include <stdint.h>

#define B_   4
#define S_   2048
#define DM   1024
#define NH   16
#define DK   64
#define BS_  (B_*S_)   // 8192

typedef unsigned long long ull;

// Scratch (device globals -- no allocation allowed)
__device__ float g_Qp[(size_t)BS_*DM];
__device__ float g_Kp[(size_t)BS_*DM];
__device__ float g_Vp[(size_t)BS_*DM];
__device__ float g_Ao[(size_t)BS_*DM];
__device__ float2 g_rope[S_ * (DK/2)];                 // [s][p] -> (cos, sin)
__device__ __nv_bfloat16 g_Wt[4][2][(size_t)DM*DM];    // [w][hi/lo][N][K] transposed weights

// ---------------------------------------------------------------------------
// Helpers
// ---------------------------------------------------------------------------
__device__ __forceinline__ uint32_t smem_u32(const void* p) {
    uint32_t a;
    asm("{ .reg .u64 t; cvta.to.shared.u64 t, %1; cvt.u32.u64 %0, t; }"
        : "=r"(a) : "l"(p));
    return a;
}

__device__ __forceinline__ void ldsm_x4(uint32_t* r, uint32_t addr) {
    asm volatile("ldmatrix.sync.aligned.m8n8.x4.shared.b16 {%0,%1,%2,%3}, [%4];"
        : "=r"(r[0]), "=r"(r[1]), "=r"(r[2]), "=r"(r[3]) : "r"(addr));
}

__device__ __forceinline__ void mma16816(float* d, const uint32_t* a, const uint32_t* b) {
    asm volatile(
        "mma.sync.aligned.m16n8k16.row.col.f32.bf16.bf16.f32 "
        "{%0,%1,%2,%3}, {%4,%5,%6,%7}, {%8,%9}, {%0,%1,%2,%3};"
        : "+f"(d[0]), "+f"(d[1]), "+f"(d[2]), "+f"(d[3])
        : "r"(a[0]), "r"(a[1]), "r"(a[2]), "r"(a[3]), "r"(b[0]), "r"(b[1]));
}

// Packed fp32x2 helpers (attention)
__device__ __forceinline__ ull ffma2(ull a, ull b, ull c) {
    ull d; asm("fma.rn.f32x2 %0, %1, %2, %3;" : "=l"(d) : "l"(a), "l"(b), "l"(c)); return d;
}
__device__ __forceinline__ ull fmul2(ull a, ull b) {
    ull d; asm("mul.rn.f32x2 %0, %1, %2;" : "=l"(d) : "l"(a), "l"(b)); return d;
}
__device__ __forceinline__ ull fadd2(ull a, ull b) {
    ull d; asm("add.rn.f32x2 %0, %1, %2;" : "=l"(d) : "l"(a), "l"(b)); return d;
}
__device__ __forceinline__ ull fpack2(float lo, float hi) {
    ull d; asm("mov.b64 %0, {%1, %2};" : "=l"(d) : "f"(lo), "f"(hi)); return d;
}
__device__ __forceinline__ float2 funpack2(ull v) {
    float lo, hi; asm("mov.b64 {%0, %1}, %2;" : "=f"(lo), "=f"(hi) : "l"(v));
    return make_float2(lo, hi);
}

// ---------------------------------------------------------------------------
// Weight transpose + bf16 hi/lo split: W[K,N] fp32 -> hi/lo bf16 [N,K]
// ---------------------------------------------------------------------------
__global__ __launch_bounds__(256) void wconv_kernel(
    const float* __restrict__ W, __nv_bfloat16* __restrict__ hi,
    __nv_bfloat16* __restrict__ lo)
{
    __shared__ float t[32][33];
    int n0 = blockIdx.x * 32, k0 = blockIdx.y * 32;
    int tx = threadIdx.x & 31, ty0 = threadIdx.x >> 5;   // 32x8

    #pragma unroll
    for (int r = 0; r < 32; r += 8)
        t[ty0 + r][tx] = W[(size_t)(k0 + ty0 + r) * DM + n0 + tx];
    __syncthreads();
    #pragma unroll
    for (int r = 0; r < 32; r += 8) {
        int n = ty0 + r;
        float x = t[tx][n];                 // W[k0+tx][n0+n]
        __nv_bfloat16 h = __float2bfloat16(x);
        hi[(size_t)(n0 + n) * DM + k0 + tx] = h;
        lo[(size_t)(n0 + n) * DM + k0 + tx] = __float2bfloat16(x - __bfloat162float(h));
    }
}

// ---------------------------------------------------------------------------
// mma.sync split-bf16 GEMM: C[M,N] = A[M,K] * B[K,N]
// A fp32 [M,K] converted inline to bf16 hi/lo; B pre-split bf16 [N,K].
// CTA 128x128, 8 warps (2x4), warp tile 64x32, K-chunk 64, 3-term split.
// smem row stride 72 bf16 (144 B) -> conflict-free ldmatrix, no swizzle.
// ---------------------------------------------------------------------------
#define KC  64
#define STR 72

__global__ __launch_bounds__(256) void mma_gemm_kernel(
    const float* __restrict__ A,
    const __nv_bfloat16* __restrict__ Bhi,
    const __nv_bfloat16* __restrict__ Blo,
    float* __restrict__ C)
{
    extern __shared__ char smem[];
    __nv_bfloat16* sAh = (__nv_bfloat16*)smem;           // [128][STR]
    __nv_bfloat16* sAl = sAh + 128 * STR;
    __nv_bfloat16* sBh = sAl + 128 * STR;
    __nv_bfloat16* sBl = sBh + 128 * STR;
    uint32_t sb  = smem_u32(smem);
    uint32_t uAh = sb;
    uint32_t uAl = uAh + 128 * STR * 2;
    uint32_t uBh = uAl + 128 * STR * 2;
    uint32_t uBl = uBh + 128 * STR * 2;

    int tid = threadIdx.x, wid = tid >> 5, lane = tid & 31;
    int wm = wid >> 2, wn = wid & 3;             // 2 x 4 warp grid
    int m0 = blockIdx.y * 128, n0 = blockIdx.x * 128;

    float acc[4][4][4];
    #pragma unroll
    for (int mt = 0; mt < 4; mt++)
        #pragma unroll
        for (int nt = 0; nt < 4; nt++)
            #pragma unroll
            for (int i = 0; i < 4; i++) acc[mt][nt][i] = 0.f;

    // ldmatrix lane addressing (canonical k-major A[M,K] / B[N,K], no .trans)
    int a_row = lane & 15;
    int a_k8  = (lane >> 4) * 8;
    int b_q   = lane >> 3, b_r = lane & 7;
    int b_nin = (b_q >> 1) * 8 + b_r;            // n offset within 16-n pair
    int b_k8  = (b_q & 1) * 8;

    for (int kc0 = 0; kc0 < DM; kc0 += KC) {
        // ---- load tiles: A fp32->hi/lo convert; B straight copies ----
        #pragma unroll
        for (int it = 0; it < 4; it++) {
            int c = tid + it * 256;              // 1024 chunks of 8 elements
            int row = c >> 3, kcol = (c & 7) * 8;
            const float4* src = (const float4*)&A[(size_t)(m0 + row) * DM + kc0 + kcol];
            float4 x0 = src[0], x1 = src[1];
            float xs[8] = {x0.x, x0.y, x0.z, x0.w, x1.x, x1.y, x1.z, x1.w};
            __nv_bfloat16 h[8], l[8];
            #pragma unroll
            for (int i = 0; i < 8; i++) {
                h[i] = __float2bfloat16(xs[i]);
                l[i] = __float2bfloat16(xs[i] - __bfloat162float(h[i]));
            }
            int off = row * STR + kcol;
            *(uint4*)&sAh[off] = *(uint4*)h;
            *(uint4*)&sAl[off] = *(uint4*)l;
            *(uint4*)&sBh[off] = *(const uint4*)&Bhi[(size_t)(n0 + row) * DM + kc0 + kcol];
            *(uint4*)&sBl[off] = *(const uint4*)&Blo[(size_t)(n0 + row) * DM + kc0 + kcol];
        }
        __syncthreads();

        #pragma unroll
        for (int ks = 0; ks < 4; ks++) {
            int k0 = ks * 16;
            uint32_t ah[4][4], al[4][4], bh[2][4], bl[2][4];
            #pragma unroll
            for (int mt = 0; mt < 4; mt++) {
                uint32_t ao = (uint32_t)(((wm * 64 + mt * 16 + a_row) * STR + k0 + a_k8) * 2);
                ldsm_x4(ah[mt], uAh + ao);
                ldsm_x4(al[mt], uAl + ao);
            }
            #pragma unroll
            for (int p = 0; p < 2; p++) {        // each x4 covers two n8 tiles
                uint32_t bo = (uint32_t)(((wn * 32 + p * 16 + b_nin) * STR + k0 + b_k8) * 2);
                ldsm_x4(bh[p], uBh + bo);
                ldsm_x4(bl[p], uBl + bo);
            }
            #pragma unroll
            for (int mt = 0; mt < 4; mt++)
                #pragma unroll
                for (int nt = 0; nt < 4; nt++) {
                    const uint32_t* bhp = &bh[nt >> 1][(nt & 1) * 2];
                    const uint32_t* blp = &bl[nt >> 1][(nt & 1) * 2];
                    mma16816(acc[mt][nt], ah[mt], bhp);
                    mma16816(acc[mt][nt], ah[mt], blp);
                    mma16816(acc[mt][nt], al[mt], bhp);
                }
        }
        __syncthreads();
    }

    // ---- epilogue: canonical C fragment layout, float2 stores ----
    int r0 = lane >> 2, c0 = (lane & 3) * 2;
    #pragma unroll
    for (int mt = 0; mt < 4; mt++)
        #pragma unroll
        for (int nt = 0; nt < 4; nt++) {
            int row = m0 + wm * 64 + mt * 16 + r0;
            int col = n0 + wn * 32 + nt * 8 + c0;
            *(float2*)&C[(size_t)row * DM + col] =
                make_float2(acc[mt][nt][0], acc[mt][nt][1]);
            *(float2*)&C[(size_t)(row + 8) * DM + col] =
                make_float2(acc[mt][nt][2], acc[mt][nt][3]);
        }
}

// ---------------------------------------------------------------------------
// RoPE: table kernel (all fp64 pow work, 65536 entries) + apply kernel.
// ---------------------------------------------------------------------------
__global__ void rope_table_kernel()
{
    int idx = blockIdx.x * blockDim.x + threadIdx.x;
    if (idx >= S_ * (DK / 2)) return;
    int p = idx & 31;
    int s = idx >> 5;
    double inv = pow(10000.0, -(double)(2 * p) / (double)DK);
    float ang = (float)s * (float)inv;
    float sn, cs;
    sincosf(ang, &sn, &cs);
    g_rope[idx] = make_float2(cs, sn);
}

__global__ void rope_apply_kernel(float* __restrict__ X)
{
    int idx = blockIdx.x * blockDim.x + threadIdx.x;  // pair index
    const int total = BS_ * NH * (DK / 2);
    if (idx >= total) return;

    int p    = idx & 31;
    int rest = idx >> 5;          // bs*NH + h
    int s    = (rest >> 4) & (S_ - 1);

    float2 cs = g_rope[s * 32 + p];
    float2* base = (float2*)(X + (size_t)rest * DK) + p;
    float2 x = *base;
    *base = make_float2(x.x * cs.x - x.y * cs.y,
                        x.x * cs.y + x.y * cs.x);
}

// ---------------------------------------------------------------------------
// Flash-style attention (fp32, packed f32x2 inner loops).
// Grid: (S/128, B*NH). Block: 128 threads, 1 query each.
// ---------------------------------------------------------------------------
__global__ __launch_bounds__(128) void attn_kernel(
    const float* __restrict__ Q, const float* __restrict__ K,
    const float* __restrict__ V, float* __restrict__ O)
{
    extern __shared__ float sm[];
    float* Ks = sm;                 // 64*64
    float* Vs = sm + 64 * 64;       // 64*64
    float* Sc = sm + 2 * 64 * 64;   // 64*128

    int tid = threadIdx.x;
    int bh  = blockIdx.y;
    int b   = bh >> 4;
    int h   = bh & 15;
    int q   = blockIdx.x * 128 + tid;

    const float scale = 0.125f;
    const ull scale2 = fpack2(scale, scale);

    ull qv[32];
    {
        const ulonglong2* qb =
            (const ulonglong2*)(Q + (((size_t)(b * S_ + q)) * NH + h) * DK);
        #pragma unroll
        for (int i = 0; i < 16; i++) {
            ulonglong2 t2 = qb[i];
            qv[2 * i]     = fmul2(t2.x, scale2);
            qv[2 * i + 1] = fmul2(t2.y, scale2);
        }
    }
    ull av[32];
    #pragma unroll
    for (int i = 0; i < 32; i++) av[i] = 0ull;
    float mval = -1e30f, lval = 0.f;

    int jrow  = tid >> 1;
    int jcol0 = (tid & 1) * 32;

    for (int t0 = 0; t0 < S_; t0 += 64) {
        const float* kb = K + (((size_t)(b * S_ + t0 + jrow)) * NH + h) * DK + jcol0;
        const float* vb = V + (((size_t)(b * S_ + t0 + jrow)) * NH + h) * DK + jcol0;
        #pragma unroll
        for (int u = 0; u < 8; u++) {
            *(float4*)&Ks[jrow * 64 + jcol0 + u * 4] = *(const float4*)(kb + u * 4);
            *(float4*)&Vs[jrow * 64 + jcol0 + u * 4] = *(const float4*)(vb + u * 4);
        }
        __syncthreads();

        float tmax = -1e30f;
        #pragma unroll 2
        for (int j = 0; j < 64; j++) {
            const ulonglong2* kr = (const ulonglong2*)&Ks[j * 64];
            ull d0 = 0ull, d1 = 0ull, d2 = 0ull, d3 = 0ull;
            #pragma unroll
            for (int i = 0; i < 8; i++) {
                ulonglong2 ka  = kr[2 * i];
                ulonglong2 kbv = kr[2 * i + 1];
                d0 = ffma2(qv[4 * i],     ka.x,  d0);
                d1 = ffma2(qv[4 * i + 1], ka.y,  d1);
                d2 = ffma2(qv[4 * i + 2], kbv.x, d2);
                d3 = ffma2(qv[4 * i + 3], kbv.y, d3);
            }
            float2 r = funpack2(fadd2(fadd2(d0, d1), fadd2(d2, d3)));
            float s = r.x + r.y;
            Sc[j * 128 + tid] = s;
            tmax = fmaxf(tmax, s);
        }

        float mnew = fmaxf(mval, tmax);
        float corr = __expf(mval - mnew);
        lval *= corr;
        {
            ull corr2 = fpack2(corr, corr);
            #pragma unroll
            for (int i = 0; i < 32; i++) av[i] = fmul2(av[i], corr2);
        }
        mval = mnew;

        #pragma unroll 2
        for (int j = 0; j < 64; j++) {
            float p = __expf(Sc[j * 128 + tid] - mval);
            lval += p;
            ull p2 = fpack2(p, p);
            const ulonglong2* vr = (const ulonglong2*)&Vs[j * 64];
            #pragma unroll
            for (int i = 0; i < 16; i++) {
                ulonglong2 vv = vr[i];
                av[2 * i]     = ffma2(p2, vv.x, av[2 * i]);
                av[2 * i + 1] = ffma2(p2, vv.y, av[2 * i + 1]);
            }
        }
        __syncthreads();
    }

    float inv = 1.f / lval;
    ull inv2 = fpack2(inv, inv);
    ulonglong2* ob = (ulonglong2*)(O + (((size_t)(b * S_ + q)) * NH + h) * DK);
    #pragma unroll
    for (int i = 0; i < 16; i++) {
        ulonglong2 v2;
        v2.x = fmul2(av[2 * i], inv2);
        v2.y = fmul2(av[2 * i + 1], inv2);
        ob[i] = v2;
    }
}

// ---------------------------------------------------------------------------
extern "C" void kernel_launch(void* const* d_in, const int* in_sizes, int n_in,
                              void* d_out, int out_size)
{
    const float* q  = (const float*)d_in[0];
    const float* k  = (const float*)d_in[1];
    const float* v  = (const float*)d_in[2];
    const float* Wq = (const float*)d_in[3];
    const float* Wk = (const float*)d_in[4];
    const float* Wv = (const float*)d_in[5];
    const float* Wo = (const float*)d_in[6];
    float* out = (float*)d_out;

    float *Qp, *Kp, *Vp, *Ao;
    __nv_bfloat16* Wt;
    cudaGetSymbolAddress((void**)&Qp, g_Qp);
    cudaGetSymbolAddress((void**)&Kp, g_Kp);
    cudaGetSymbolAddress((void**)&Vp, g_Vp);
    cudaGetSymbolAddress((void**)&Ao, g_Ao);
    cudaGetSymbolAddress((void**)&Wt, g_Wt);

    const size_t WSZ = (size_t)DM * DM;
    __nv_bfloat16* Wqh = Wt + 0 * 2 * WSZ; __nv_bfloat16* Wql = Wqh + WSZ;
    __nv_bfloat16* Wkh = Wt + 1 * 2 * WSZ; __nv_bfloat16* Wkl = Wkh + WSZ;
    __nv_bfloat16* Wvh = Wt + 2 * 2 * WSZ; __nv_bfloat16* Wvl = Wvh + WSZ;
    __nv_bfloat16* Woh = Wt + 3 * 2 * WSZ; __nv_bfloat16* Wol = Woh + WSZ;

    // Weight transpose + split (and RoPE table) up front
    dim3 wgrid(DM / 32, DM / 32);
    wconv_kernel<<<wgrid, 256>>>(Wq, Wqh, Wql);
    wconv_kernel<<<wgrid, 256>>>(Wk, Wkh, Wkl);
    wconv_kernel<<<wgrid, 256>>>(Wv, Wvh, Wvl);
    wconv_kernel<<<wgrid, 256>>>(Wo, Woh, Wol);
    rope_table_kernel<<<(S_ * 32 + 255) / 256, 256>>>();

    const int GEMM_SMEM = 4 * 128 * STR * 2;   // 73728 B
    cudaFuncSetAttribute(mma_gemm_kernel, cudaFuncAttributeMaxDynamicSharedMemorySize, GEMM_SMEM);
    dim3 ggrid(DM / 128, BS_ / 128);   // (8, 64)
    mma_gemm_kernel<<<ggrid, 256, GEMM_SMEM>>>(q, Wqh, Wql, Qp);
    mma_gemm_kernel<<<ggrid, 256, GEMM_SMEM>>>(k, Wkh, Wkl, Kp);
    mma_gemm_kernel<<<ggrid, 256, GEMM_SMEM>>>(v, Wvh, Wvl, Vp);

    const int total_pairs = BS_ * NH * (DK / 2);
    int rblocks = (total_pairs + 255) / 256;
    rope_apply_kernel<<<rblocks, 256>>>(Qp);
    rope_apply_kernel<<<rblocks, 256>>>(Kp);

    const int ATTN_SMEM = (2 * 64 * 64 + 64 * 128) * sizeof(float);  // 64 KB
    cudaFuncSetAttribute(attn_kernel, cudaFuncAttributeMaxDynamicSharedMemorySize, ATTN_SMEM);
    dim3 ablk(S_ / 128, B_ * NH);   // (16, 64)
    attn_kernel<<<ablk, 128, ATTN_SMEM>>>(Qp, Kp, Vp, Ao);

    mma_gemm_kernel<<<ggrid, 256, GEMM_SMEM>>>(Ao, Woh, Wol, out);
}

// round 14
// speedup vs baseline: 2.3892x; 1.4315x over previous
#include <cuda_runtime.h>
#include <cuda_bf16.h>
#include <math.h>
#include <stdint.h>

#define B_   4
#define S_   2048
#define DM   1024
#define NH   16
#define DK   64
#define BS_  (B_*S_)   // 8192

// Scratch (device globals -- no allocation allowed)
__device__ float g_Qp[(size_t)BS_*DM];
__device__ float g_Kp[(size_t)BS_*DM];
__device__ float g_Vp[(size_t)BS_*DM];
__device__ float g_Ao[(size_t)BS_*DM];
__device__ float2 g_rope[S_ * (DK/2)];                 // [s][p] -> (cos, sin)
__device__ __nv_bfloat16 g_Wt[4][2][(size_t)DM*DM];    // [w][hi/lo][N][K] transposed weights
__device__ __nv_bfloat16 g_Kh[(size_t)BS_*DM];
__device__ __nv_bfloat16 g_Kl[(size_t)BS_*DM];
__device__ __nv_bfloat16 g_Vh[(size_t)BS_*DM];
__device__ __nv_bfloat16 g_Vl[(size_t)BS_*DM];

// ---------------------------------------------------------------------------
// Helpers
// ---------------------------------------------------------------------------
__device__ __forceinline__ uint32_t smem_u32(const void* p) {
    uint32_t a;
    asm("{ .reg .u64 t; cvta.to.shared.u64 t, %1; cvt.u32.u64 %0, t; }"
        : "=r"(a) : "l"(p));
    return a;
}

__device__ __forceinline__ void ldsm_x4(uint32_t* r, uint32_t addr) {
    asm volatile("ldmatrix.sync.aligned.m8n8.x4.shared.b16 {%0,%1,%2,%3}, [%4];"
        : "=r"(r[0]), "=r"(r[1]), "=r"(r[2]), "=r"(r[3]) : "r"(addr));
}
__device__ __forceinline__ void ldsm_x4_t(uint32_t* r, uint32_t addr) {
    asm volatile("ldmatrix.sync.aligned.m8n8.x4.trans.shared.b16 {%0,%1,%2,%3}, [%4];"
        : "=r"(r[0]), "=r"(r[1]), "=r"(r[2]), "=r"(r[3]) : "r"(addr));
}

__device__ __forceinline__ void mma16816(float* d, const uint32_t* a, const uint32_t* b) {
    asm volatile(
        "mma.sync.aligned.m16n8k16.row.col.f32.bf16.bf16.f32 "
        "{%0,%1,%2,%3}, {%4,%5,%6,%7}, {%8,%9}, {%0,%1,%2,%3};"
        : "+f"(d[0]), "+f"(d[1]), "+f"(d[2]), "+f"(d[3])
        : "r"(a[0]), "r"(a[1]), "r"(a[2]), "r"(a[3]), "r"(b[0]), "r"(b[1]));
}

// Fast exp on the FMA pipe: x<=0 assumed; rel err ~5e-5.
__device__ __forceinline__ float fexp(float x) {
    x = fmaxf(x, -87.0f);
    float t = fmaf(x, 1.4426950408889634f, 12582912.0f);
    float i = t - 12582912.0f;                      // round-to-nearest integer
    float f = fmaf(x, 1.4426950408889634f, -i);     // frac in [-0.5, 0.5]
    float p = 0.0096181291f;
    p = fmaf(p, f, 0.0555041086f);
    p = fmaf(p, f, 0.2402265069f);
    p = fmaf(p, f, 0.6931471806f);
    p = fmaf(p, f, 1.0f);
    int e = __float2int_rn(i);
    return __int_as_float(__float_as_int(p) + (e << 23));
}

__device__ __forceinline__ uint32_t packbf2(float a, float b) {
    __nv_bfloat162 v = __floats2bfloat162_rn(a, b);   // .x = a (low), .y = b (high)
    return *(uint32_t*)&v;
}

// ---------------------------------------------------------------------------
// Weight transpose + bf16 hi/lo split: W[K,N] fp32 -> hi/lo bf16 [N,K]
// ---------------------------------------------------------------------------
__global__ __launch_bounds__(256) void wconv_kernel(
    const float* __restrict__ W, __nv_bfloat16* __restrict__ hi,
    __nv_bfloat16* __restrict__ lo)
{
    __shared__ float t[32][33];
    int n0 = blockIdx.x * 32, k0 = blockIdx.y * 32;
    int tx = threadIdx.x & 31, ty0 = threadIdx.x >> 5;   // 32x8

    #pragma unroll
    for (int r = 0; r < 32; r += 8)
        t[ty0 + r][tx] = W[(size_t)(k0 + ty0 + r) * DM + n0 + tx];
    __syncthreads();
    #pragma unroll
    for (int r = 0; r < 32; r += 8) {
        int n = ty0 + r;
        float x = t[tx][n];                 // W[k0+tx][n0+n]
        __nv_bfloat16 h = __float2bfloat16(x);
        hi[(size_t)(n0 + n) * DM + k0 + tx] = h;
        lo[(size_t)(n0 + n) * DM + k0 + tx] = __float2bfloat16(x - __bfloat162float(h));
    }
}

// ---------------------------------------------------------------------------
// mma.sync split-bf16 GEMM (validated R12): C[M,N] = A[M,K] * B[K,N]
// ---------------------------------------------------------------------------
#define KC  64
#define STR 72

__global__ __launch_bounds__(256) void mma_gemm_kernel(
    const float* __restrict__ A,
    const __nv_bfloat16* __restrict__ Bhi,
    const __nv_bfloat16* __restrict__ Blo,
    float* __restrict__ C)
{
    extern __shared__ char smem[];
    __nv_bfloat16* sAh = (__nv_bfloat16*)smem;           // [128][STR]
    __nv_bfloat16* sAl = sAh + 128 * STR;
    __nv_bfloat16* sBh = sAl + 128 * STR;
    __nv_bfloat16* sBl = sBh + 128 * STR;
    uint32_t sb  = smem_u32(smem);
    uint32_t uAh = sb;
    uint32_t uAl = uAh + 128 * STR * 2;
    uint32_t uBh = uAl + 128 * STR * 2;
    uint32_t uBl = uBh + 128 * STR * 2;

    int tid = threadIdx.x, wid = tid >> 5, lane = tid & 31;
    int wm = wid >> 2, wn = wid & 3;             // 2 x 4 warp grid
    int m0 = blockIdx.y * 128, n0 = blockIdx.x * 128;

    float acc[4][4][4];
    #pragma unroll
    for (int mt = 0; mt < 4; mt++)
        #pragma unroll
        for (int nt = 0; nt < 4; nt++)
            #pragma unroll
            for (int i = 0; i < 4; i++) acc[mt][nt][i] = 0.f;

    int a_row = lane & 15;
    int a_k8  = (lane >> 4) * 8;
    int b_q   = lane >> 3, b_r = lane & 7;
    int b_nin = (b_q >> 1) * 8 + b_r;
    int b_k8  = (b_q & 1) * 8;

    for (int kc0 = 0; kc0 < DM; kc0 += KC) {
        #pragma unroll
        for (int it = 0; it < 4; it++) {
            int c = tid + it * 256;
            int row = c >> 3, kcol = (c & 7) * 8;
            const float4* src = (const float4*)&A[(size_t)(m0 + row) * DM + kc0 + kcol];
            float4 x0 = src[0], x1 = src[1];
            float xs[8] = {x0.x, x0.y, x0.z, x0.w, x1.x, x1.y, x1.z, x1.w};
            __nv_bfloat16 h[8], l[8];
            #pragma unroll
            for (int i = 0; i < 8; i++) {
                h[i] = __float2bfloat16(xs[i]);
                l[i] = __float2bfloat16(xs[i] - __bfloat162float(h[i]));
            }
            int off = row * STR + kcol;
            *(uint4*)&sAh[off] = *(uint4*)h;
            *(uint4*)&sAl[off] = *(uint4*)l;
            *(uint4*)&sBh[off] = *(const uint4*)&Bhi[(size_t)(n0 + row) * DM + kc0 + kcol];
            *(uint4*)&sBl[off] = *(const uint4*)&Blo[(size_t)(n0 + row) * DM + kc0 + kcol];
        }
        __syncthreads();

        #pragma unroll
        for (int ks = 0; ks < 4; ks++) {
            int k0 = ks * 16;
            uint32_t ah[4][4], al[4][4], bh[2][4], bl[2][4];
            #pragma unroll
            for (int mt = 0; mt < 4; mt++) {
                uint32_t ao = (uint32_t)(((wm * 64 + mt * 16 + a_row) * STR + k0 + a_k8) * 2);
                ldsm_x4(ah[mt], uAh + ao);
                ldsm_x4(al[mt], uAl + ao);
            }
            #pragma unroll
            for (int p = 0; p < 2; p++) {
                uint32_t bo = (uint32_t)(((wn * 32 + p * 16 + b_nin) * STR + k0 + b_k8) * 2);
                ldsm_x4(bh[p], uBh + bo);
                ldsm_x4(bl[p], uBl + bo);
            }
            #pragma unroll
            for (int mt = 0; mt < 4; mt++)
                #pragma unroll
                for (int nt = 0; nt < 4; nt++) {
                    const uint32_t* bhp = &bh[nt >> 1][(nt & 1) * 2];
                    const uint32_t* blp = &bl[nt >> 1][(nt & 1) * 2];
                    mma16816(acc[mt][nt], ah[mt], bhp);
                    mma16816(acc[mt][nt], ah[mt], blp);
                    mma16816(acc[mt][nt], al[mt], bhp);
                }
        }
        __syncthreads();
    }

    int r0 = lane >> 2, c0 = (lane & 3) * 2;
    #pragma unroll
    for (int mt = 0; mt < 4; mt++)
        #pragma unroll
        for (int nt = 0; nt < 4; nt++) {
            int row = m0 + wm * 64 + mt * 16 + r0;
            int col = n0 + wn * 32 + nt * 8 + c0;
            *(float2*)&C[(size_t)row * DM + col] =
                make_float2(acc[mt][nt][0], acc[mt][nt][1]);
            *(float2*)&C[(size_t)(row + 8) * DM + col] =
                make_float2(acc[mt][nt][2], acc[mt][nt][3]);
        }
}

// ---------------------------------------------------------------------------
// RoPE: table kernel + apply kernel.
// ---------------------------------------------------------------------------
__global__ void rope_table_kernel()
{
    int idx = blockIdx.x * blockDim.x + threadIdx.x;
    if (idx >= S_ * (DK / 2)) return;
    int p = idx & 31;
    int s = idx >> 5;
    double inv = pow(10000.0, -(double)(2 * p) / (double)DK);
    float ang = (float)s * (float)inv;
    float sn, cs;
    sincosf(ang, &sn, &cs);
    g_rope[idx] = make_float2(cs, sn);
}

__global__ void rope_apply_kernel(float* __restrict__ X)
{
    int idx = blockIdx.x * blockDim.x + threadIdx.x;  // pair index
    const int total = BS_ * NH * (DK / 2);
    if (idx >= total) return;

    int p    = idx & 31;
    int rest = idx >> 5;          // bs*NH + h
    int s    = (rest >> 4) & (S_ - 1);

    float2 cs = g_rope[s * 32 + p];
    float2* base = (float2*)(X + (size_t)rest * DK) + p;
    float2 x = *base;
    *base = make_float2(x.x * cs.x - x.y * cs.y,
                        x.x * cs.y + x.y * cs.x);
}

// ---------------------------------------------------------------------------
// K/V fp32 -> bf16 hi/lo pre-conversion (K post-rope).
// ---------------------------------------------------------------------------
__global__ __launch_bounds__(256) void kvconv_kernel(
    const float* __restrict__ K, const float* __restrict__ V)
{
    int i = blockIdx.x * blockDim.x + threadIdx.x;    // group of 4 elements
    const int total = BS_ * DM / 4;
    if (i >= total) return;

    float4 k4 = ((const float4*)K)[i];
    float4 v4 = ((const float4*)V)[i];
    __nv_bfloat16 kh[4], kl[4], vh[4], vl[4];
    float ks[4] = {k4.x, k4.y, k4.z, k4.w};
    float vs[4] = {v4.x, v4.y, v4.z, v4.w};
    #pragma unroll
    for (int j = 0; j < 4; j++) {
        kh[j] = __float2bfloat16(ks[j]);
        kl[j] = __float2bfloat16(ks[j] - __bfloat162float(kh[j]));
        vh[j] = __float2bfloat16(vs[j]);
        vl[j] = __float2bfloat16(vs[j] - __bfloat162float(vh[j]));
    }
    ((uint2*)g_Kh)[i] = *(uint2*)kh;
    ((uint2*)g_Kl)[i] = *(uint2*)kl;
    ((uint2*)g_Vh)[i] = *(uint2*)vh;
    ((uint2*)g_Vl)[i] = *(uint2*)vl;
}

// ---------------------------------------------------------------------------
// Tensor-core flash attention, split-bf16 (3-term) QK^T and PV.
// Grid (S/128, B*NH), block 256 (8 warps, one m16 row-tile each).
// smem: Q phase 2x[128][72] bf16 aliased with KV phase 4x[64][72] bf16.
// ---------------------------------------------------------------------------
#define AST 72
#define ATTN_SMEM (4 * 64 * AST * 2)   // == 2*128*AST*2 = 36864 B

__global__ __launch_bounds__(256) void attn_mma_kernel(
    const float* __restrict__ Q,
    const __nv_bfloat16* __restrict__ Kh, const __nv_bfloat16* __restrict__ Kl,
    const __nv_bfloat16* __restrict__ Vh, const __nv_bfloat16* __restrict__ Vl,
    float* __restrict__ O)
{
    extern __shared__ char smem[];
    __nv_bfloat16* sQh = (__nv_bfloat16*)smem;        // [128][AST]
    __nv_bfloat16* sKh = (__nv_bfloat16*)smem;        // [64][AST] (aliased)
    __nv_bfloat16* sKl = sKh + 64 * AST;
    __nv_bfloat16* sVh = sKl + 64 * AST;
    __nv_bfloat16* sVl = sVh + 64 * AST;
    __nv_bfloat16* sQl = sQh + 128 * AST;
    uint32_t sb  = smem_u32(smem);
    uint32_t uQh = sb, uQl = sb + 128 * AST * 2;
    uint32_t uKh = sb, uKl = sb + 64 * AST * 2;
    uint32_t uVh = uKl + 64 * AST * 2, uVl = uVh + 64 * AST * 2;

    int tid = threadIdx.x, wid = tid >> 5, lane = tid & 31;
    int b = blockIdx.y >> 4, h = blockIdx.y & 15;
    int qbase = blockIdx.x * 128;

    // ---- load Q tile (128x64 fp32), scale, split into smem ----
    #pragma unroll
    for (int it = 0; it < 4; it++) {
        int c = tid + it * 256;                       // 1024 chunks of 8
        int row = c >> 3, col8 = (c & 7) * 8;
        const float4* src =
            (const float4*)&Q[(size_t)(b * S_ + qbase + row) * DM + h * DK + col8];
        float4 x0 = src[0], x1 = src[1];
        float xs[8] = {x0.x, x0.y, x0.z, x0.w, x1.x, x1.y, x1.z, x1.w};
        __nv_bfloat16 hh[8], ll[8];
        #pragma unroll
        for (int i = 0; i < 8; i++) {
            float v = xs[i] * 0.125f;                 // 1/sqrt(DK)
            hh[i] = __float2bfloat16(v);
            ll[i] = __float2bfloat16(v - __bfloat162float(hh[i]));
        }
        *(uint4*)&sQh[row * AST + col8] = *(uint4*)hh;
        *(uint4*)&sQl[row * AST + col8] = *(uint4*)ll;
    }
    __syncthreads();

    // ---- Q fragments (m16 x k16 per k-step), hi/lo ----
    uint32_t qh[4][4], ql[4][4];
    {
        int mrow = wid * 16 + (lane & 15);
        int kblk = (lane >> 4) * 8;
        #pragma unroll
        for (int ks = 0; ks < 4; ks++) {
            uint32_t ao = (uint32_t)((mrow * AST + ks * 16 + kblk) * 2);
            ldsm_x4(qh[ks], uQh + ao);
            ldsm_x4(ql[ks], uQl + ao);
        }
    }
    __syncthreads();

    float oacc[8][4];
    #pragma unroll
    for (int j = 0; j < 8; j++)
        #pragma unroll
        for (int i = 0; i < 4; i++) oacc[j][i] = 0.f;
    float m0 = -1e30f, m1 = -1e30f, l0 = 0.f, l1 = 0.f;

    int b_nin = (lane >> 4) * 8 + (lane & 7);         // non-trans B addressing
    int b_k8  = ((lane >> 3) & 1) * 8;
    int t_row = lane & 15;                            // trans addressing (V)
    int t_c8  = (lane >> 4) * 8;

    for (int t0 = 0; t0 < S_; t0 += 64) {
        // ---- load K/V tiles (bf16 hi/lo, 64x64 each) ----
        #pragma unroll
        for (int it = 0; it < 2; it++) {
            int c = tid + it * 256;                   // 512 chunks of 8
            int row = c >> 3, col8 = (c & 7) * 8;
            size_t src = (size_t)(b * S_ + t0 + row) * DM + h * DK + col8;
            int off = row * AST + col8;
            *(uint4*)&sKh[off] = *(const uint4*)&Kh[src];
            *(uint4*)&sKl[off] = *(const uint4*)&Kl[src];
            *(uint4*)&sVh[off] = *(const uint4*)&Vh[src];
            *(uint4*)&sVl[off] = *(const uint4*)&Vl[src];
        }
        __syncthreads();

        // ---- S = Q K^T (8 n8-tiles of keys), 3-term split ----
        float sacc[8][4];
        #pragma unroll
        for (int j = 0; j < 8; j++)
            #pragma unroll
            for (int i = 0; i < 4; i++) sacc[j][i] = 0.f;

        #pragma unroll
        for (int p = 0; p < 4; p++) {
            #pragma unroll
            for (int ks = 0; ks < 4; ks++) {
                uint32_t bh4[4], bl4[4];
                uint32_t bo = (uint32_t)(((p * 16 + b_nin) * AST + ks * 16 + b_k8) * 2);
                ldsm_x4(bh4, uKh + bo);
                ldsm_x4(bl4, uKl + bo);
                mma16816(sacc[2 * p],     qh[ks], bh4);
                mma16816(sacc[2 * p],     qh[ks], bl4);
                mma16816(sacc[2 * p],     ql[ks], bh4);
                mma16816(sacc[2 * p + 1], qh[ks], bh4 + 2);
                mma16816(sacc[2 * p + 1], qh[ks], bl4 + 2);
                mma16816(sacc[2 * p + 1], ql[ks], bh4 + 2);
            }
        }

        // ---- online softmax (rows r0 = lane>>2 and r0+8) ----
        float tm0 = -1e30f, tm1 = -1e30f;
        #pragma unroll
        for (int j = 0; j < 8; j++) {
            tm0 = fmaxf(tm0, fmaxf(sacc[j][0], sacc[j][1]));
            tm1 = fmaxf(tm1, fmaxf(sacc[j][2], sacc[j][3]));
        }
        tm0 = fmaxf(tm0, __shfl_xor_sync(0xffffffff, tm0, 1));
        tm0 = fmaxf(tm0, __shfl_xor_sync(0xffffffff, tm0, 2));
        tm1 = fmaxf(tm1, __shfl_xor_sync(0xffffffff, tm1, 1));
        tm1 = fmaxf(tm1, __shfl_xor_sync(0xffffffff, tm1, 2));

        float nm0 = fmaxf(m0, tm0), nm1 = fmaxf(m1, tm1);
        float cr0 = fexp(m0 - nm0), cr1 = fexp(m1 - nm1);
        m0 = nm0; m1 = nm1;
        l0 *= cr0; l1 *= cr1;
        #pragma unroll
        for (int j = 0; j < 8; j++) {
            oacc[j][0] *= cr0; oacc[j][1] *= cr0;
            oacc[j][2] *= cr1; oacc[j][3] *= cr1;
        }

        // ---- P = exp(S - m): build A-fragments (hi/lo) in registers ----
        uint32_t pfh[4][4], pfl[4][4];
        float rs0 = 0.f, rs1 = 0.f;
        #pragma unroll
        for (int j = 0; j < 8; j++) {
            float p0 = fexp(sacc[j][0] - m0), p1 = fexp(sacc[j][1] - m0);
            float p2 = fexp(sacc[j][2] - m1), p3 = fexp(sacc[j][3] - m1);
            rs0 += p0 + p1; rs1 += p2 + p3;
            // hi/lo split per element
            __nv_bfloat162 h01 = __floats2bfloat162_rn(p0, p1);
            __nv_bfloat162 h23 = __floats2bfloat162_rn(p2, p3);
            float l0f = p0 - __bfloat162float(h01.x);
            float l1f = p1 - __bfloat162float(h01.y);
            float l2f = p2 - __bfloat162float(h23.x);
            float l3f = p3 - __bfloat162float(h23.y);
            int kt = j >> 1, sub = (j & 1) * 2;
            pfh[kt][sub]     = *(uint32_t*)&h01;
            pfh[kt][sub + 1] = *(uint32_t*)&h23;
            pfl[kt][sub]     = packbf2(l0f, l1f);
            pfl[kt][sub + 1] = packbf2(l2f, l3f);
        }
        rs0 += __shfl_xor_sync(0xffffffff, rs0, 1);
        rs0 += __shfl_xor_sync(0xffffffff, rs0, 2);
        rs1 += __shfl_xor_sync(0xffffffff, rs1, 1);
        rs1 += __shfl_xor_sync(0xffffffff, rs1, 2);
        l0 += rs0; l1 += rs1;

        // ---- O += P V (trans-ldmatrix V), 3-term split ----
        #pragma unroll
        for (int p = 0; p < 4; p++) {
            #pragma unroll
            for (int kt = 0; kt < 4; kt++) {
                uint32_t vh4[4], vl4[4];
                uint32_t vo = (uint32_t)(((kt * 16 + t_row) * AST + p * 16 + t_c8) * 2);
                ldsm_x4_t(vh4, uVh + vo);
                ldsm_x4_t(vl4, uVl + vo);
                mma16816(oacc[2 * p],     pfh[kt], vh4);
                mma16816(oacc[2 * p],     pfl[kt], vh4);
                mma16816(oacc[2 * p],     pfh[kt], vl4);
                mma16816(oacc[2 * p + 1], pfh[kt], vh4 + 2);
                mma16816(oacc[2 * p + 1], pfl[kt], vh4 + 2);
                mma16816(oacc[2 * p + 1], pfh[kt], vl4 + 2);
            }
        }
        __syncthreads();
    }

    // ---- epilogue ----
    float i0 = 1.f / l0, i1 = 1.f / l1;
    int r0 = lane >> 2, c2 = (lane & 3) * 2;
    int row0 = b * S_ + qbase + wid * 16 + r0;
    #pragma unroll
    for (int j = 0; j < 8; j++) {
        int col = h * DK + j * 8 + c2;
        *(float2*)&O[(size_t)row0 * DM + col] =
            make_float2(oacc[j][0] * i0, oacc[j][1] * i0);
        *(float2*)&O[(size_t)(row0 + 8) * DM + col] =
            make_float2(oacc[j][2] * i1, oacc[j][3] * i1);
    }
}

// ---------------------------------------------------------------------------
extern "C" void kernel_launch(void* const* d_in, const int* in_sizes, int n_in,
                              void* d_out, int out_size)
{
    const float* q  = (const float*)d_in[0];
    const float* k  = (const float*)d_in[1];
    const float* v  = (const float*)d_in[2];
    const float* Wq = (const float*)d_in[3];
    const float* Wk = (const float*)d_in[4];
    const float* Wv = (const float*)d_in[5];
    const float* Wo = (const float*)d_in[6];
    float* out = (float*)d_out;

    float *Qp, *Kp, *Vp, *Ao;
    __nv_bfloat16 *Wt, *Kh, *Kl, *Vh, *Vl;
    cudaGetSymbolAddress((void**)&Qp, g_Qp);
    cudaGetSymbolAddress((void**)&Kp, g_Kp);
    cudaGetSymbolAddress((void**)&Vp, g_Vp);
    cudaGetSymbolAddress((void**)&Ao, g_Ao);
    cudaGetSymbolAddress((void**)&Wt, g_Wt);
    cudaGetSymbolAddress((void**)&Kh, g_Kh);
    cudaGetSymbolAddress((void**)&Kl, g_Kl);
    cudaGetSymbolAddress((void**)&Vh, g_Vh);
    cudaGetSymbolAddress((void**)&Vl, g_Vl);

    const size_t WSZ = (size_t)DM * DM;
    __nv_bfloat16* Wqh = Wt + 0 * 2 * WSZ; __nv_bfloat16* Wql = Wqh + WSZ;
    __nv_bfloat16* Wkh = Wt + 1 * 2 * WSZ; __nv_bfloat16* Wkl = Wkh + WSZ;
    __nv_bfloat16* Wvh = Wt + 2 * 2 * WSZ; __nv_bfloat16* Wvl = Wvh + WSZ;
    __nv_bfloat16* Woh = Wt + 3 * 2 * WSZ; __nv_bfloat16* Wol = Woh + WSZ;

    dim3 wgrid(DM / 32, DM / 32);
    wconv_kernel<<<wgrid, 256>>>(Wq, Wqh, Wql);
    wconv_kernel<<<wgrid, 256>>>(Wk, Wkh, Wkl);
    wconv_kernel<<<wgrid, 256>>>(Wv, Wvh, Wvl);
    wconv_kernel<<<wgrid, 256>>>(Wo, Woh, Wol);
    rope_table_kernel<<<(S_ * 32 + 255) / 256, 256>>>();

    const int GEMM_SMEM = 4 * 128 * STR * 2;   // 73728 B
    cudaFuncSetAttribute(mma_gemm_kernel, cudaFuncAttributeMaxDynamicSharedMemorySize, GEMM_SMEM);
    dim3 ggrid(DM / 128, BS_ / 128);   // (8, 64)
    mma_gemm_kernel<<<ggrid, 256, GEMM_SMEM>>>(q, Wqh, Wql, Qp);
    mma_gemm_kernel<<<ggrid, 256, GEMM_SMEM>>>(k, Wkh, Wkl, Kp);
    mma_gemm_kernel<<<ggrid, 256, GEMM_SMEM>>>(v, Wvh, Wvl, Vp);

    const int total_pairs = BS_ * NH * (DK / 2);
    int rblocks = (total_pairs + 255) / 256;
    rope_apply_kernel<<<rblocks, 256>>>(Qp);
    rope_apply_kernel<<<rblocks, 256>>>(Kp);

    kvconv_kernel<<<(BS_ * DM / 4 + 255) / 256, 256>>>(Kp, Vp);

    cudaFuncSetAttribute(attn_mma_kernel, cudaFuncAttributeMaxDynamicSharedMemorySize, ATTN_SMEM);
    dim3 agrid(S_ / 128, B_ * NH);   // (16, 64)
    attn_mma_kernel<<<agrid, 256, ATTN_SMEM>>>(Qp, Kh, Kl, Vh, Vl, Ao);

    mma_gemm_kernel<<<ggrid, 256, GEMM_SMEM>>>(Ao, Woh, Wol, out);
}